// round 1
// baseline (speedup 1.0000x reference)
#include <cuda_runtime.h>

#define SEQ   8192
#define DIM   2048
#define H     16
#define DH    128
#define PDIM  512
#define EPSF  1e-5f
#define NCHUNK 128
#define CHS   (SEQ / NCHUNK)   // 64 rows per chunk

// ---------------- scratch (device globals: no runtime allocation) ----------
__device__ __align__(16) float g_Wq[H * DIM];          // q-folded key proj [16,2048]
__device__ float                g_bq[H];
__device__ float                g_attn[H * SEQ];       // logits -> softmax weights
__device__ __align__(16) float g_ypart[NCHUNK][H * DIM]; // partial attn-weighted x sums
__device__ __align__(16) float g_y[H * DIM];           // y[h,:] = sum_s attn[h,s] x[s,:]
__device__ __align__(16) float g_x1[DIM];              // attention output (1 row)
__device__ float                g_h1[PDIM];            // proj1 pre-LN
__device__ __align__(16) float g_r[PDIM];              // relu(LN(h1))
__device__ __align__(16) float g_add[DIM];             // final residual add vector

// ---- k0: Wq[h,j] = sum_d q[h*128+d] * W_kv[(h*128+d), j];  bq[h] likewise ----
__global__ void k0_wq(const float* __restrict__ q,
                      const float* __restrict__ Wkv,
                      const float* __restrict__ bkv) {
    int idx = blockIdx.x * 256 + threadIdx.x;          // 32768 threads
    int h = idx >> 11, j = idx & (DIM - 1);
    const float* qh = q + h * DH;
    const float* w  = Wkv + (size_t)h * DH * DIM + j;
    float acc = 0.f;
    #pragma unroll 8
    for (int d = 0; d < DH; ++d)
        acc += qh[d] * w[(size_t)d * DIM];
    g_Wq[idx] = acc;
    if (idx < H) {
        float b = 0.f;
        for (int d = 0; d < DH; ++d) b += q[idx * DH + d] * bkv[idx * DH + d];
        g_bq[idx] = b;
    }
}

// ---- k1: logits[h,s] = (x[s,:] . Wq[h,:] + bq[h]) / sqrt(128) --------------
// One warp handles 2 sequence rows; lanes stripe j with float4.
__global__ void __launch_bounds__(256) k1_logits(const float* __restrict__ x) {
    int warp = (blockIdx.x * 256 + threadIdx.x) >> 5;  // 4096 warps
    int lane = threadIdx.x & 31;
    int s0 = warp * 2;
    const float4* xr0 = (const float4*)(x + (size_t)s0 * DIM);
    const float4* xr1 = (const float4*)(x + (size_t)(s0 + 1) * DIM);
    const float4* wq  = (const float4*)g_Wq;
    float acc0[H], acc1[H];
    #pragma unroll
    for (int h = 0; h < H; ++h) { acc0[h] = 0.f; acc1[h] = 0.f; }
    #pragma unroll 4
    for (int it = 0; it < DIM / 128; ++it) {           // 16 iters
        int j = it * 32 + lane;
        float4 a = xr0[j];
        float4 b = xr1[j];
        #pragma unroll
        for (int h = 0; h < H; ++h) {
            float4 w = wq[h * (DIM / 4) + j];
            acc0[h] += a.x * w.x + a.y * w.y + a.z * w.z + a.w * w.w;
            acc1[h] += b.x * w.x + b.y * w.y + b.z * w.z + b.w * w.w;
        }
    }
    const float scale = 0.08838834764831845f;          // 1/sqrt(128)
    #pragma unroll
    for (int h = 0; h < H; ++h) {
        float v0 = acc0[h], v1 = acc1[h];
        #pragma unroll
        for (int o = 16; o > 0; o >>= 1) {
            v0 += __shfl_xor_sync(0xffffffffu, v0, o);
            v1 += __shfl_xor_sync(0xffffffffu, v1, o);
        }
        if (lane == 0) {
            float bq = g_bq[h];
            g_attn[h * SEQ + s0]     = (v0 + bq) * scale;
            g_attn[h * SEQ + s0 + 1] = (v1 + bq) * scale;
        }
    }
}

// ---- k2: softmax along s, one block per head --------------------------------
__global__ void k2_softmax() {
    int h = blockIdx.x, tid = threadIdx.x;             // 256 threads
    __shared__ float red[256];
    float* row = g_attn + h * SEQ;
    float m = -1e30f;
    for (int i = tid; i < SEQ; i += 256) m = fmaxf(m, row[i]);
    red[tid] = m; __syncthreads();
    for (int o = 128; o > 0; o >>= 1) {
        if (tid < o) red[tid] = fmaxf(red[tid], red[tid + o]);
        __syncthreads();
    }
    m = red[0]; __syncthreads();
    float s = 0.f;
    for (int i = tid; i < SEQ; i += 256) {
        float e = __expf(row[i] - m);
        row[i] = e;
        s += e;
    }
    red[tid] = s; __syncthreads();
    for (int o = 128; o > 0; o >>= 1) {
        if (tid < o) red[tid] += red[tid + o];
        __syncthreads();
    }
    float inv = 1.f / red[0];
    __syncthreads();
    for (int i = tid; i < SEQ; i += 256) row[i] *= inv;
}

// ---- k3: partial y[h,j] over an s-chunk -------------------------------------
// 512 threads, each owns 4 j columns (float4), all 16 heads. attn chunk in smem.
__global__ void __launch_bounds__(512) k3_yaccum(const float* __restrict__ x) {
    int c = blockIdx.x;                                // chunk id, 128 chunks
    int tid = threadIdx.x;                             // 512 threads
    __shared__ float sat[H * CHS];                     // 16 x 64 attn weights
    for (int i = tid; i < H * CHS; i += 512) {
        int h = i / CHS, sl = i % CHS;
        sat[i] = g_attn[h * SEQ + c * CHS + sl];
    }
    __syncthreads();
    float4 acc[H];
    #pragma unroll
    for (int h = 0; h < H; ++h) acc[h] = make_float4(0.f, 0.f, 0.f, 0.f);
    const float4* x4 = (const float4*)x;
    int base = c * CHS;
    #pragma unroll 2
    for (int sl = 0; sl < CHS; ++sl) {
        float4 xv = x4[(size_t)(base + sl) * (DIM / 4) + tid];
        #pragma unroll
        for (int h = 0; h < H; ++h) {
            float a = sat[h * CHS + sl];
            acc[h].x += a * xv.x; acc[h].y += a * xv.y;
            acc[h].z += a * xv.z; acc[h].w += a * xv.w;
        }
    }
    float4* yp = (float4*)g_ypart[c];
    #pragma unroll
    for (int h = 0; h < H; ++h) yp[h * (DIM / 4) + tid] = acc[h];
}

// ---- k3b: reduce partials -> g_y --------------------------------------------
__global__ void k3b_reduce() {
    int i = blockIdx.x * 256 + threadIdx.x;            // 32768 threads
    float s = 0.f;
    for (int c = 0; c < NCHUNK; ++c) s += g_ypart[c][i];
    g_y[i] = s;
}

// ---- k4: x1[i] = W_v[i,:] . y[h(i),:] + b_v[i]; one warp per output ---------
__global__ void k4_x1(const float* __restrict__ Wkv, const float* __restrict__ bkv) {
    int warp = (blockIdx.x * 256 + threadIdx.x) >> 5;  // 2048 warps
    int lane = threadIdx.x & 31;
    int h = warp >> 7;
    const float4* w = (const float4*)(Wkv + (size_t)(DIM + warp) * DIM);
    const float4* y = (const float4*)(g_y + h * DIM);
    float a = 0.f;
    for (int it = lane; it < DIM / 4; it += 32) {
        float4 wv = w[it], yv = y[it];
        a += wv.x * yv.x + wv.y * yv.y + wv.z * yv.z + wv.w * yv.w;
    }
    #pragma unroll
    for (int o = 16; o > 0; o >>= 1) a += __shfl_xor_sync(0xffffffffu, a, o);
    if (lane == 0) g_x1[warp] = a + bkv[DIM + warp];
}

// ---- k5: h1 = W_p1 @ x1 + b_p1; one warp per output -------------------------
__global__ void k5_p1(const float* __restrict__ Wp1, const float* __restrict__ bp1) {
    int warp = (blockIdx.x * 256 + threadIdx.x) >> 5;  // 512 warps
    int lane = threadIdx.x & 31;
    const float4* w = (const float4*)(Wp1 + (size_t)warp * DIM);
    const float4* v = (const float4*)g_x1;
    float a = 0.f;
    for (int it = lane; it < DIM / 4; it += 32) {
        float4 wv = w[it], vv = v[it];
        a += wv.x * vv.x + wv.y * vv.y + wv.z * vv.z + wv.w * vv.w;
    }
    #pragma unroll
    for (int o = 16; o > 0; o >>= 1) a += __shfl_xor_sync(0xffffffffu, a, o);
    if (lane == 0) g_h1[warp] = a + bp1[warp];
}

// ---- k6: LayerNorm(512) + relu; single block of 512 -------------------------
__global__ void k6_ln(const float* __restrict__ lnw, const float* __restrict__ lnb) {
    __shared__ float red[PDIM];
    int tid = threadIdx.x;
    float v = g_h1[tid];
    red[tid] = v; __syncthreads();
    for (int o = 256; o > 0; o >>= 1) {
        if (tid < o) red[tid] += red[tid + o];
        __syncthreads();
    }
    float mu = red[0] * (1.f / PDIM); __syncthreads();
    float d = v - mu;
    red[tid] = d * d; __syncthreads();
    for (int o = 256; o > 0; o >>= 1) {
        if (tid < o) red[tid] += red[tid + o];
        __syncthreads();
    }
    float var = red[0] * (1.f / PDIM);
    float n = d * rsqrtf(var + EPSF) * lnw[tid] + lnb[tid];
    g_r[tid] = fmaxf(n, 0.f);
}

// ---- k7: add vector = W_p2 @ r + b_p2; one warp per output ------------------
__global__ void k7_p2(const float* __restrict__ Wp2, const float* __restrict__ bp2) {
    int warp = (blockIdx.x * 256 + threadIdx.x) >> 5;  // 2048 warps
    int lane = threadIdx.x & 31;
    const float4* w = (const float4*)(Wp2 + (size_t)warp * PDIM);
    const float4* v = (const float4*)g_r;
    float a = 0.f;
    for (int it = lane; it < PDIM / 4; it += 32) {     // 4 iters
        float4 wv = w[it], vv = v[it];
        a += wv.x * vv.x + wv.y * vv.y + wv.z * vv.z + wv.w * vv.w;
    }
    #pragma unroll
    for (int o = 16; o > 0; o >>= 1) a += __shfl_xor_sync(0xffffffffu, a, o);
    if (lane == 0) g_add[warp] = a + bp2[warp];
}

// ---- k8: out = x + broadcast(add) -------------------------------------------
__global__ void __launch_bounds__(256) k8_resid(const float* __restrict__ x,
                                                float* __restrict__ out) {
    size_t i = (size_t)blockIdx.x * 256 + threadIdx.x; // float4 index
    const float4* x4 = (const float4*)x;
    const float4* a4 = (const float4*)g_add;
    float4 xv = x4[i];
    float4 av = a4[i & (DIM / 4 - 1)];
    float4 o;
    o.x = xv.x + av.x; o.y = xv.y + av.y; o.z = xv.z + av.z; o.w = xv.w + av.w;
    ((float4*)out)[i] = o;
}

extern "C" void kernel_launch(void* const* d_in, const int* in_sizes, int n_in,
                              void* d_out, int out_size) {
    const float* x    = (const float*)d_in[0];
    const float* q    = (const float*)d_in[1];
    const float* Wkv  = (const float*)d_in[2];
    const float* bkv  = (const float*)d_in[3];
    const float* Wp1  = (const float*)d_in[4];
    const float* bp1  = (const float*)d_in[5];
    const float* Wp2  = (const float*)d_in[6];
    const float* bp2  = (const float*)d_in[7];
    const float* lnw  = (const float*)d_in[8];
    const float* lnb  = (const float*)d_in[9];
    float* out = (float*)d_out;

    k0_wq<<<(H * DIM) / 256, 256>>>(q, Wkv, bkv);
    k1_logits<<<(SEQ / 2) / 8, 256>>>(x);              // 512 blocks, 8 warps, 2 rows/warp
    k2_softmax<<<H, 256>>>();
    k3_yaccum<<<NCHUNK, 512>>>(x);
    k3b_reduce<<<(H * DIM) / 256, 256>>>();
    k4_x1<<<DIM / 8, 256>>>(Wkv, bkv);                 // 2048 warps
    k5_p1<<<PDIM / 8, 256>>>(Wp1, bp1);                // 512 warps
    k6_ln<<<1, PDIM>>>(lnw, lnb);
    k7_p2<<<DIM / 8, 256>>>(Wp2, bp2);                 // 2048 warps
    k8_resid<<<(SEQ * DIM / 4) / 256, 256>>>(x, out);  // 16384 blocks
}